// round 3
// baseline (speedup 1.0000x reference)
#include <cuda_runtime.h>
#include <cstdint>
#include <math_constants.h>

#define BB 2
#define TQ 1024
#define TK 1024
#define DD 64
#define QW 2                 // queries per warp
#define WARPS 2
#define THREADS (WARPS * 32)
#define QT (WARPS * QW)      // 4 query rows per block
#define KT 64                // key tile
#define NT (TK / KT)         // 16 tiles

__device__ __forceinline__ float tanh_fast(float x) {
    float y;
    asm("tanh.approx.f32 %0, %1;" : "=f"(y) : "f"(x));
    return y;
}

__device__ __forceinline__ void cp16(void* dst, const void* src) {
    unsigned d = (unsigned)__cvta_generic_to_shared(dst);
    asm volatile("cp.async.cg.shared.global [%0], [%1], 16;" :: "r"(d), "l"(src));
}
__device__ __forceinline__ void cp_commit() { asm volatile("cp.async.commit_group;"); }
template <int N>
__device__ __forceinline__ void cp_wait() { asm volatile("cp.async.wait_group %0;" :: "n"(N)); }

__global__ __launch_bounds__(THREADS)
void addattn_kernel(const float* __restrict__ Q,
                    const float* __restrict__ V,
                    const float* __restrict__ S,
                    float* __restrict__ O) {
    // V tile as float4 chunks, XOR-swizzled: chunk c of key k at k*16 + (c ^ (k&15)).
    __shared__ __align__(16) float4 v_s[2][KT * 16];   // 2 x 16 KB
    __shared__ __align__(16) float4 q_s[QT * 16];      // 1 KB
    __shared__ __align__(16) float4 sc_s[16];          // 256 B
    __shared__ __align__(16) float  p_s[QT][KT];       // 1 KB

    const int tid  = threadIdx.x;
    const int lane = tid & 31;
    const int warp = tid >> 5;
    const int b    = blockIdx.y;
    const int q0   = blockIdx.x * QT;

    // Load Q tile + scale. QT*16 = 64 = THREADS.
    const float4* Q4 = (const float4*)(Q + ((size_t)b * TQ + q0) * DD);
    q_s[tid] = Q4[tid];
    if (tid < 16) sc_s[tid] = ((const float4*)S)[tid];

    const float4* V4 = (const float4*)(V + (size_t)b * TK * DD);

    // Prefetch V tile 0: 1024 chunks / 64 threads = 16 per thread
    #pragma unroll
    for (int i = 0; i < 16; i++) {
        int id = tid + i * THREADS;
        int k = id >> 4, c = id & 15;
        cp16(&v_s[0][k * 16 + (c ^ (k & 15))], &V4[(size_t)k * 16 + c]);
    }
    cp_commit();

    // per-query online-softmax state (2 queries per warp)
    float m0 = -CUDART_INF_F, l0 = 0.f, ox0 = 0.f, oy0 = 0.f;
    float m1 = -CUDART_INF_F, l1 = 0.f, ox1 = 0.f, oy1 = 0.f;
    const int sw = lane & 15;
    const int qa = warp * QW;        // first query row (in block) of this warp

    for (int t = 0; t < NT; ++t) {
        if (t + 1 < NT) {
            #pragma unroll
            for (int i = 0; i < 16; i++) {
                int id = tid + i * THREADS;
                int k = id >> 4, c = id & 15;
                cp16(&v_s[(t + 1) & 1][k * 16 + (c ^ (k & 15))],
                     &V4[(size_t)(t + 1) * KT * 16 + k * 16 + c]);
            }
            cp_commit();
            cp_wait<1>();
        } else {
            cp_wait<0>();
        }
        __syncthreads();

        const float4* vb = v_s[t & 1];

        // ---- Phase 1: scores for 2 queries. lane -> keys {lane, lane+32}.
        float a00 = 0.f, a01 = 0.f;   // query 0, key halves
        float a10 = 0.f, a11 = 0.f;   // query 1
        #pragma unroll
        for (int c = 0; c < 16; c++) {
            float4 qv0 = q_s[(qa + 0) * 16 + c];   // warp-uniform broadcast
            float4 qv1 = q_s[(qa + 1) * 16 + c];
            float4 sc  = sc_s[c];                  // broadcast
            float4 u = vb[lane * 16 + (c ^ sw)];
            float4 w = vb[(lane + 32) * 16 + (c ^ sw)];
            a00 = fmaf(sc.x, tanh_fast(qv0.x + u.x), a00);
            a00 = fmaf(sc.y, tanh_fast(qv0.y + u.y), a00);
            a00 = fmaf(sc.z, tanh_fast(qv0.z + u.z), a00);
            a00 = fmaf(sc.w, tanh_fast(qv0.w + u.w), a00);
            a01 = fmaf(sc.x, tanh_fast(qv0.x + w.x), a01);
            a01 = fmaf(sc.y, tanh_fast(qv0.y + w.y), a01);
            a01 = fmaf(sc.z, tanh_fast(qv0.z + w.z), a01);
            a01 = fmaf(sc.w, tanh_fast(qv0.w + w.w), a01);
            a10 = fmaf(sc.x, tanh_fast(qv1.x + u.x), a10);
            a10 = fmaf(sc.y, tanh_fast(qv1.y + u.y), a10);
            a10 = fmaf(sc.z, tanh_fast(qv1.z + u.z), a10);
            a10 = fmaf(sc.w, tanh_fast(qv1.w + u.w), a10);
            a11 = fmaf(sc.x, tanh_fast(qv1.x + w.x), a11);
            a11 = fmaf(sc.y, tanh_fast(qv1.y + w.y), a11);
            a11 = fmaf(sc.z, tanh_fast(qv1.z + w.z), a11);
            a11 = fmaf(sc.w, tanh_fast(qv1.w + w.w), a11);
        }

        // ---- Phase 2: online softmax per query (in-warp reductions)
        {
            float tm = fmaxf(a00, a01);
            #pragma unroll
            for (int off = 16; off > 0; off >>= 1)
                tm = fmaxf(tm, __shfl_xor_sync(0xffffffffu, tm, off));
            float mn = fmaxf(m0, tm);
            float alpha = __expf(m0 - mn);
            float p0 = __expf(a00 - mn), p1 = __expf(a01 - mn);
            float ts = p0 + p1;
            #pragma unroll
            for (int off = 16; off > 0; off >>= 1)
                ts += __shfl_xor_sync(0xffffffffu, ts, off);
            l0 = l0 * alpha + ts; m0 = mn; ox0 *= alpha; oy0 *= alpha;
            p_s[qa + 0][lane] = p0; p_s[qa + 0][lane + 32] = p1;
        }
        {
            float tm = fmaxf(a10, a11);
            #pragma unroll
            for (int off = 16; off > 0; off >>= 1)
                tm = fmaxf(tm, __shfl_xor_sync(0xffffffffu, tm, off));
            float mn = fmaxf(m1, tm);
            float alpha = __expf(m1 - mn);
            float p0 = __expf(a10 - mn), p1 = __expf(a11 - mn);
            float ts = p0 + p1;
            #pragma unroll
            for (int off = 16; off > 0; off >>= 1)
                ts += __shfl_xor_sync(0xffffffffu, ts, off);
            l1 = l1 * alpha + ts; m1 = mn; ox1 *= alpha; oy1 *= alpha;
            p_s[qa + 1][lane] = p0; p_s[qa + 1][lane + 32] = p1;
        }
        __syncwarp();

        // ---- Phase 3: output accumulation. lane -> dims {2*lane, 2*lane+1}.
        // One V read feeds both queries.
        const float* pr0 = p_s[qa + 0];
        const float* pr1 = p_s[qa + 1];
        const int c2 = lane >> 1, half = lane & 1;
        #pragma unroll
        for (int k = 0; k < KT; k += 4) {
            float4 pp0 = *(const float4*)&pr0[k];  // broadcast
            float4 pp1 = *(const float4*)&pr1[k];
            float pv0[4] = {pp0.x, pp0.y, pp0.z, pp0.w};
            float pv1[4] = {pp1.x, pp1.y, pp1.z, pp1.w};
            #pragma unroll
            for (int i = 0; i < 4; i++) {
                int kk = k + i;
                const float2* ch = (const float2*)&vb[kk * 16 + (c2 ^ (kk & 15))];
                float2 vv = ch[half];
                ox0 = fmaf(pv0[i], vv.x, ox0);
                oy0 = fmaf(pv0[i], vv.y, oy0);
                ox1 = fmaf(pv1[i], vv.x, ox1);
                oy1 = fmaf(pv1[i], vv.y, oy1);
            }
        }
        __syncthreads();  // all warps done with vb before it is refilled
    }

    {
        const float inv = 1.f / l0;
        float2 r; r.x = ox0 * inv; r.y = oy0 * inv;
        ((float2*)(O + ((size_t)b * TQ + q0 + qa + 0) * DD))[lane] = r;
    }
    {
        const float inv = 1.f / l1;
        float2 r; r.x = ox1 * inv; r.y = oy1 * inv;
        ((float2*)(O + ((size_t)b * TQ + q0 + qa + 1) * DD))[lane] = r;
    }
}

extern "C" void kernel_launch(void* const* d_in, const int* in_sizes, int n_in,
                              void* d_out, int out_size) {
    const float* Q = (const float*)d_in[0];   // query [B, Tq, D] f32
    const float* V = (const float*)d_in[1];   // value [B, Tk, D] f32
    const float* S = (const float*)d_in[2];   // scale [D] f32
    float* O = (float*)d_out;                 // out   [B, Tq, D] f32
    dim3 grid(TQ / QT, BB);
    addattn_kernel<<<grid, THREADS>>>(Q, V, S, O);
}

// round 4
// speedup vs baseline: 1.0447x; 1.0447x over previous
#include <cuda_runtime.h>
#include <cstdint>
#include <math_constants.h>

#define BB 2
#define TQ 1024
#define TK 1024
#define DD 64
#define QW 2                 // queries per warp
#define WARPS 4              // 128 threads -> one warp per SMSP
#define THREADS (WARPS * 32)
#define QT (WARPS * QW)      // 8 query rows per block
#define KT 32                // key tile (lane = key)
#define NT (TK / KT)         // 32 tiles
#define NB 4                 // V smem buffers

__device__ __forceinline__ float tanh_fast(float x) {
    float y;
    asm("tanh.approx.f32 %0, %1;" : "=f"(y) : "f"(x));
    return y;
}

__device__ __forceinline__ void cp16(void* dst, const void* src) {
    unsigned d = (unsigned)__cvta_generic_to_shared(dst);
    asm volatile("cp.async.cg.shared.global [%0], [%1], 16;" :: "r"(d), "l"(src));
}
__device__ __forceinline__ void cp_commit() { asm volatile("cp.async.commit_group;"); }
template <int N>
__device__ __forceinline__ void cp_wait() { asm volatile("cp.async.wait_group %0;" :: "n"(N)); }

// V tile as float4 chunks, XOR-swizzled: chunk c of key k at k*16 + (c ^ (k&15)).
__device__ __forceinline__ void prefetch_tile(float4* dst, const float4* V4, int tt, int tid) {
    #pragma unroll
    for (int i = 0; i < 4; i++) {            // 512 chunks / 128 threads
        int id = tid + i * THREADS;
        int k = id >> 4, c = id & 15;
        cp16(&dst[k * 16 + (c ^ (k & 15))], &V4[(size_t)tt * KT * 16 + k * 16 + c]);
    }
    cp_commit();
}

__global__ __launch_bounds__(THREADS)
void addattn_kernel(const float* __restrict__ Q,
                    const float* __restrict__ V,
                    const float* __restrict__ S,
                    float* __restrict__ O) {
    __shared__ __align__(16) float4 v_s[NB][KT * 16];   // 32 KB
    __shared__ __align__(16) float4 q_s[QT * 16];       // 2 KB
    __shared__ __align__(16) float4 sc_s[16];           // 256 B
    __shared__ __align__(16) float  p_s[2][QT][KT];     // 2 KB

    const int tid  = threadIdx.x;
    const int lane = tid & 31;
    const int warp = tid >> 5;
    const int b    = blockIdx.y;
    const int q0   = blockIdx.x * QT;

    const float4* Q4 = (const float4*)(Q + ((size_t)b * TQ + q0) * DD);
    q_s[tid] = Q4[tid];                       // QT*16 == 128 == THREADS
    if (tid < 16) sc_s[tid] = ((const float4*)S)[tid];

    const float4* V4 = (const float4*)(V + (size_t)b * TK * DD);
    prefetch_tile(v_s[0], V4, 0, tid);
    prefetch_tile(v_s[1], V4, 1, tid);

    float l0 = 0.f, l1 = 0.f;
    float ox0 = 0.f, oy0 = 0.f, ox1 = 0.f, oy1 = 0.f;
    const int sw   = lane & 15;               // swizzle key for this lane's key row
    const int c2   = lane >> 1, half = lane & 1;
    const int qa   = warp * QW;

    // ---------- iter t = 0 : scores only (no phase-3 to fuse yet) ----------
    {
        cp_wait<1>();
        __syncthreads();
        prefetch_tile(v_s[2], V4, 2, tid);
        const float4* vb = v_s[0];
        float a00 = 0.f, a10 = 0.f;
        #pragma unroll
        for (int c = 0; c < 16; c++) {
            float4 qv0 = q_s[(qa + 0) * 16 + c];
            float4 qv1 = q_s[(qa + 1) * 16 + c];
            float4 sc  = sc_s[c];
            float4 u   = vb[lane * 16 + (c ^ sw)];
            a00 = fmaf(sc.x, tanh_fast(qv0.x + u.x), a00);
            a00 = fmaf(sc.y, tanh_fast(qv0.y + u.y), a00);
            a00 = fmaf(sc.z, tanh_fast(qv0.z + u.z), a00);
            a00 = fmaf(sc.w, tanh_fast(qv0.w + u.w), a00);
            a10 = fmaf(sc.x, tanh_fast(qv1.x + u.x), a10);
            a10 = fmaf(sc.y, tanh_fast(qv1.y + u.y), a10);
            a10 = fmaf(sc.z, tanh_fast(qv1.z + u.z), a10);
            a10 = fmaf(sc.w, tanh_fast(qv1.w + u.w), a10);
        }
        float p00 = __expf(a00), p10 = __expf(a10);
        l0 += p00; l1 += p10;
        p_s[0][qa + 0][lane] = p00;
        p_s[0][qa + 1][lane] = p10;
        __syncwarp();
    }

    // ---------- iters t = 1..NT-1 : fused P1(t) + P3(t-1) ----------
    for (int t = 1; t < NT; ++t) {
        if (t + 1 < NT) cp_wait<1>(); else cp_wait<0>();
        __syncthreads();
        if (t + 2 < NT) prefetch_tile(v_s[(t + 2) & 3], V4, t + 2, tid);

        const float4* vb  = v_s[t & 3];
        const float4* vp  = v_s[(t + 3) & 3];          // (t-1) & 3
        const float*  pr0 = p_s[(t + 1) & 1][qa + 0];  // (t-1) & 1
        const float*  pr1 = p_s[(t + 1) & 1][qa + 1];

        float a00 = 0.f, a10 = 0.f;
        #pragma unroll
        for (int c = 0; c < 16; c++) {
            // --- phase 1 chunk (tile t), 8 tanh ---
            float4 qv0 = q_s[(qa + 0) * 16 + c];
            float4 qv1 = q_s[(qa + 1) * 16 + c];
            float4 sc  = sc_s[c];
            float4 u   = vb[lane * 16 + (c ^ sw)];
            a00 = fmaf(sc.x, tanh_fast(qv0.x + u.x), a00);
            a00 = fmaf(sc.y, tanh_fast(qv0.y + u.y), a00);
            a00 = fmaf(sc.z, tanh_fast(qv0.z + u.z), a00);
            a00 = fmaf(sc.w, tanh_fast(qv0.w + u.w), a00);
            a10 = fmaf(sc.x, tanh_fast(qv1.x + u.x), a10);
            a10 = fmaf(sc.y, tanh_fast(qv1.y + u.y), a10);
            a10 = fmaf(sc.z, tanh_fast(qv1.z + u.z), a10);
            a10 = fmaf(sc.w, tanh_fast(qv1.w + u.w), a10);

            // --- phase 3 chunk (tile t-1), keys 2c, 2c+1 ---
            {
                const int k0 = 2 * c, k1 = 2 * c + 1;
                float2 pq0 = *(const float2*)&pr0[k0];
                float2 pq1 = *(const float2*)&pr1[k0];
                float2 va = ((const float2*)&vp[k0 * 16 + (c2 ^ (k0 & 15))])[half];
                float2 vc = ((const float2*)&vp[k1 * 16 + (c2 ^ (k1 & 15))])[half];
                ox0 = fmaf(pq0.x, va.x, ox0); oy0 = fmaf(pq0.x, va.y, oy0);
                ox1 = fmaf(pq1.x, va.x, ox1); oy1 = fmaf(pq1.x, va.y, oy1);
                ox0 = fmaf(pq0.y, vc.x, ox0); oy0 = fmaf(pq0.y, vc.y, oy0);
                ox1 = fmaf(pq1.y, vc.x, ox1); oy1 = fmaf(pq1.y, vc.y, oy1);
            }
        }
        float p00 = __expf(a00), p10 = __expf(a10);
        l0 += p00; l1 += p10;
        p_s[t & 1][qa + 0][lane] = p00;
        p_s[t & 1][qa + 1][lane] = p10;
        __syncwarp();
    }

    // ---------- epilogue: P3 for tile NT-1 ----------
    {
        const float4* vp  = v_s[(NT - 1) & 3];
        const float*  pr0 = p_s[(NT - 1) & 1][qa + 0];
        const float*  pr1 = p_s[(NT - 1) & 1][qa + 1];
        #pragma unroll
        for (int c = 0; c < 16; c++) {
            const int k0 = 2 * c, k1 = 2 * c + 1;
            float2 pq0 = *(const float2*)&pr0[k0];
            float2 pq1 = *(const float2*)&pr1[k0];
            float2 va = ((const float2*)&vp[k0 * 16 + (c2 ^ (k0 & 15))])[half];
            float2 vc = ((const float2*)&vp[k1 * 16 + (c2 ^ (k1 & 15))])[half];
            ox0 = fmaf(pq0.x, va.x, ox0); oy0 = fmaf(pq0.x, va.y, oy0);
            ox1 = fmaf(pq1.x, va.x, ox1); oy1 = fmaf(pq1.x, va.y, oy1);
            ox0 = fmaf(pq0.y, vc.x, ox0); oy0 = fmaf(pq0.y, vc.y, oy0);
            ox1 = fmaf(pq1.y, vc.x, ox1); oy1 = fmaf(pq1.y, vc.y, oy1);
        }
    }

    // ---------- final l reduction (once per kernel) + output ----------
    #pragma unroll
    for (int off = 16; off > 0; off >>= 1) {
        l0 += __shfl_xor_sync(0xffffffffu, l0, off);
        l1 += __shfl_xor_sync(0xffffffffu, l1, off);
    }
    {
        const float inv = 1.f / l0;
        float2 r; r.x = ox0 * inv; r.y = oy0 * inv;
        ((float2*)(O + ((size_t)b * TQ + q0 + qa + 0) * DD))[lane] = r;
    }
    {
        const float inv = 1.f / l1;
        float2 r; r.x = ox1 * inv; r.y = oy1 * inv;
        ((float2*)(O + ((size_t)b * TQ + q0 + qa + 1) * DD))[lane] = r;
    }
}

extern "C" void kernel_launch(void* const* d_in, const int* in_sizes, int n_in,
                              void* d_out, int out_size) {
    const float* Q = (const float*)d_in[0];   // query [B, Tq, D] f32
    const float* V = (const float*)d_in[1];   // value [B, Tk, D] f32
    const float* S = (const float*)d_in[2];   // scale [D] f32
    float* O = (float*)d_out;                 // out   [B, Tq, D] f32
    dim3 grid(TQ / QT, BB);
    addattn_kernel<<<grid, THREADS>>>(Q, V, S, O);
}

// round 5
// speedup vs baseline: 1.2290x; 1.1764x over previous
#include <cuda_runtime.h>
#include <cstdint>
#include <math_constants.h>

#define BB 2
#define TQ 1024
#define TK 1024
#define DD 64
#define QW 2                 // queries per warp
#define WARPS 4              // 128 threads -> one warp per SMSP
#define THREADS (WARPS * 32)
#define QT (WARPS * QW)      // 8 query rows per block
#define KT 32                // key tile (lane = key)
#define KSPLIT 4
#define KB (TK / KSPLIT)     // 256 keys per block
#define NT (KB / KT)         // 8 tiles
#define NB 4                 // V smem buffers
#define NROW (BB * TQ)       // 2048 output rows

// scratch: unnormalized partials per k-split
__device__ float g_po[KSPLIT][NROW * DD];   // 2 MB
__device__ float g_pl[KSPLIT][NROW];        // 32 KB

__device__ __forceinline__ float tanh_fast(float x) {
    float y;
    asm("tanh.approx.f32 %0, %1;" : "=f"(y) : "f"(x));
    return y;
}

__device__ __forceinline__ void cp16(void* dst, const void* src) {
    unsigned d = (unsigned)__cvta_generic_to_shared(dst);
    asm volatile("cp.async.cg.shared.global [%0], [%1], 16;" :: "r"(d), "l"(src));
}
__device__ __forceinline__ void cp_commit() { asm volatile("cp.async.commit_group;"); }
template <int N>
__device__ __forceinline__ void cp_wait() { asm volatile("cp.async.wait_group %0;" :: "n"(N)); }

// V tile as float4 chunks, XOR-swizzled: chunk c of key k at k*16 + (c ^ (k&15)).
__device__ __forceinline__ void prefetch_tile(float4* dst, const float4* V4, int tt, int tid) {
    #pragma unroll
    for (int i = 0; i < 4; i++) {            // 512 chunks / 128 threads
        int id = tid + i * THREADS;
        int k = id >> 4, c = id & 15;
        cp16(&dst[k * 16 + (c ^ (k & 15))], &V4[(size_t)tt * KT * 16 + k * 16 + c]);
    }
    cp_commit();
}

__global__ __launch_bounds__(THREADS, 5)
void addattn_kernel(const float* __restrict__ Q,
                    const float* __restrict__ V,
                    const float* __restrict__ S) {
    __shared__ __align__(16) float4 v_s[NB][KT * 16];   // 32 KB
    __shared__ __align__(16) float4 q_s[QT * 16];       // 2 KB
    __shared__ __align__(16) float4 sc_s[16];           // 256 B
    __shared__ __align__(16) float  p_s[2][QT][KT];     // 2 KB

    const int tid  = threadIdx.x;
    const int lane = tid & 31;
    const int warp = tid >> 5;
    const int b    = blockIdx.y;
    const int ks   = blockIdx.z;
    const int q0   = blockIdx.x * QT;

    const float4* Q4 = (const float4*)(Q + ((size_t)b * TQ + q0) * DD);
    q_s[tid] = Q4[tid];                       // QT*16 == 128 == THREADS
    if (tid < 16) sc_s[tid] = ((const float4*)S)[tid];

    // this split's key range: [ks*KB, (ks+1)*KB)
    const float4* V4 = (const float4*)(V + ((size_t)b * TK + (size_t)ks * KB) * DD);
    prefetch_tile(v_s[0], V4, 0, tid);
    prefetch_tile(v_s[1], V4, 1, tid);

    float l0 = 0.f, l1 = 0.f;
    float ox0 = 0.f, oy0 = 0.f, ox1 = 0.f, oy1 = 0.f;
    const int sw   = lane & 15;               // swizzle key for this lane's key row
    const int c2   = lane >> 1, half = lane & 1;
    const int qa   = warp * QW;

    // ---------- iter t = 0 : scores only ----------
    {
        cp_wait<1>();
        __syncthreads();
        prefetch_tile(v_s[2], V4, 2, tid);
        const float4* vb = v_s[0];
        float a00 = 0.f, a10 = 0.f;
        #pragma unroll
        for (int c = 0; c < 16; c++) {
            float4 qv0 = q_s[(qa + 0) * 16 + c];
            float4 qv1 = q_s[(qa + 1) * 16 + c];
            float4 sc  = sc_s[c];
            float4 u   = vb[lane * 16 + (c ^ sw)];
            a00 = fmaf(sc.x, tanh_fast(qv0.x + u.x), a00);
            a00 = fmaf(sc.y, tanh_fast(qv0.y + u.y), a00);
            a00 = fmaf(sc.z, tanh_fast(qv0.z + u.z), a00);
            a00 = fmaf(sc.w, tanh_fast(qv0.w + u.w), a00);
            a10 = fmaf(sc.x, tanh_fast(qv1.x + u.x), a10);
            a10 = fmaf(sc.y, tanh_fast(qv1.y + u.y), a10);
            a10 = fmaf(sc.z, tanh_fast(qv1.z + u.z), a10);
            a10 = fmaf(sc.w, tanh_fast(qv1.w + u.w), a10);
        }
        float p00 = __expf(a00), p10 = __expf(a10);
        l0 += p00; l1 += p10;
        p_s[0][qa + 0][lane] = p00;
        p_s[0][qa + 1][lane] = p10;
        __syncwarp();
    }

    // ---------- iters t = 1..NT-1 : fused P1(t) + P3(t-1) ----------
    for (int t = 1; t < NT; ++t) {
        if (t + 1 < NT) cp_wait<1>(); else cp_wait<0>();
        __syncthreads();
        if (t + 2 < NT) prefetch_tile(v_s[(t + 2) & 3], V4, t + 2, tid);

        const float4* vb  = v_s[t & 3];
        const float4* vp  = v_s[(t + 3) & 3];          // (t-1) & 3
        const float*  pr0 = p_s[(t + 1) & 1][qa + 0];  // (t-1) & 1
        const float*  pr1 = p_s[(t + 1) & 1][qa + 1];

        float a00 = 0.f, a10 = 0.f;
        #pragma unroll
        for (int c = 0; c < 16; c++) {
            // --- phase 1 chunk (tile t), 8 tanh ---
            float4 qv0 = q_s[(qa + 0) * 16 + c];
            float4 qv1 = q_s[(qa + 1) * 16 + c];
            float4 sc  = sc_s[c];
            float4 u   = vb[lane * 16 + (c ^ sw)];
            a00 = fmaf(sc.x, tanh_fast(qv0.x + u.x), a00);
            a00 = fmaf(sc.y, tanh_fast(qv0.y + u.y), a00);
            a00 = fmaf(sc.z, tanh_fast(qv0.z + u.z), a00);
            a00 = fmaf(sc.w, tanh_fast(qv0.w + u.w), a00);
            a10 = fmaf(sc.x, tanh_fast(qv1.x + u.x), a10);
            a10 = fmaf(sc.y, tanh_fast(qv1.y + u.y), a10);
            a10 = fmaf(sc.z, tanh_fast(qv1.z + u.z), a10);
            a10 = fmaf(sc.w, tanh_fast(qv1.w + u.w), a10);

            // --- phase 3 chunk (tile t-1), keys 2c, 2c+1 ---
            {
                const int k0 = 2 * c, k1 = 2 * c + 1;
                float2 pq0 = *(const float2*)&pr0[k0];
                float2 pq1 = *(const float2*)&pr1[k0];
                float2 va = ((const float2*)&vp[k0 * 16 + (c2 ^ (k0 & 15))])[half];
                float2 vc = ((const float2*)&vp[k1 * 16 + (c2 ^ (k1 & 15))])[half];
                ox0 = fmaf(pq0.x, va.x, ox0); oy0 = fmaf(pq0.x, va.y, oy0);
                ox1 = fmaf(pq1.x, va.x, ox1); oy1 = fmaf(pq1.x, va.y, oy1);
                ox0 = fmaf(pq0.y, vc.x, ox0); oy0 = fmaf(pq0.y, vc.y, oy0);
                ox1 = fmaf(pq1.y, vc.x, ox1); oy1 = fmaf(pq1.y, vc.y, oy1);
            }
        }
        float p00 = __expf(a00), p10 = __expf(a10);
        l0 += p00; l1 += p10;
        p_s[t & 1][qa + 0][lane] = p00;
        p_s[t & 1][qa + 1][lane] = p10;
        __syncwarp();
    }

    // ---------- epilogue: P3 for tile NT-1 ----------
    {
        const float4* vp  = v_s[(NT - 1) & 3];
        const float*  pr0 = p_s[(NT - 1) & 1][qa + 0];
        const float*  pr1 = p_s[(NT - 1) & 1][qa + 1];
        #pragma unroll
        for (int c = 0; c < 16; c++) {
            const int k0 = 2 * c, k1 = 2 * c + 1;
            float2 pq0 = *(const float2*)&pr0[k0];
            float2 pq1 = *(const float2*)&pr1[k0];
            float2 va = ((const float2*)&vp[k0 * 16 + (c2 ^ (k0 & 15))])[half];
            float2 vc = ((const float2*)&vp[k1 * 16 + (c2 ^ (k1 & 15))])[half];
            ox0 = fmaf(pq0.x, va.x, ox0); oy0 = fmaf(pq0.x, va.y, oy0);
            ox1 = fmaf(pq1.x, va.x, ox1); oy1 = fmaf(pq1.x, va.y, oy1);
            ox0 = fmaf(pq0.y, vc.x, ox0); oy0 = fmaf(pq0.y, vc.y, oy0);
            ox1 = fmaf(pq1.y, vc.x, ox1); oy1 = fmaf(pq1.y, vc.y, oy1);
        }
    }

    // ---------- write unnormalized partials ----------
    #pragma unroll
    for (int off = 16; off > 0; off >>= 1) {
        l0 += __shfl_xor_sync(0xffffffffu, l0, off);
        l1 += __shfl_xor_sync(0xffffffffu, l1, off);
    }
    const int row0 = b * TQ + q0 + qa;
    {
        float2 r; r.x = ox0; r.y = oy0;
        ((float2*)&g_po[ks][(size_t)(row0 + 0) * DD])[lane] = r;
        if (lane == 0) g_pl[ks][row0 + 0] = l0;
    }
    {
        float2 r; r.x = ox1; r.y = oy1;
        ((float2*)&g_po[ks][(size_t)(row0 + 1) * DD])[lane] = r;
        if (lane == 0) g_pl[ks][row0 + 1] = l1;
    }
}

// Combine: out[row,d] = sum_s po[s][row,d] / sum_s pl[s][row]
__global__ __launch_bounds__(256)
void combine_kernel(float* __restrict__ O) {
    const int tid = blockIdx.x * 256 + threadIdx.x;   // one float2 each
    const int row = tid >> 5;
    const int d2  = tid & 31;
    float l = g_pl[0][row] + g_pl[1][row] + g_pl[2][row] + g_pl[3][row];
    float2 acc = make_float2(0.f, 0.f);
    #pragma unroll
    for (int s = 0; s < KSPLIT; s++) {
        float2 v = ((const float2*)&g_po[s][(size_t)row * DD])[d2];
        acc.x += v.x; acc.y += v.y;
    }
    const float inv = 1.f / l;
    float2 r; r.x = acc.x * inv; r.y = acc.y * inv;
    ((float2*)O)[tid] = r;
}

extern "C" void kernel_launch(void* const* d_in, const int* in_sizes, int n_in,
                              void* d_out, int out_size) {
    const float* Q = (const float*)d_in[0];   // query [B, Tq, D] f32
    const float* V = (const float*)d_in[1];   // value [B, Tk, D] f32
    const float* S = (const float*)d_in[2];   // scale [D] f32
    float* O = (float*)d_out;                 // out   [B, Tq, D] f32
    dim3 grid(TQ / QT, BB, KSPLIT);           // 128 x 2 x 4 = 1024 blocks
    addattn_kernel<<<grid, THREADS>>>(Q, V, S);
    combine_kernel<<<(NROW * DD / 2) / 256, 256>>>(O);
}